// round 1
// baseline (speedup 1.0000x reference)
#include <cuda_runtime.h>
#include <cstdint>

#define NCTA 128
#define TPB  512
#define HDIM 1024
#define G4   4096

// Persistent scratch (no allocations allowed): tagged h exchange + x-gate cache.
__device__ unsigned long long g_hbuf[2][HDIM];
__device__ float g_xg[G4];

// ---------------- PTX helpers ----------------
__device__ __forceinline__ unsigned long long ld_relaxed_u64(const unsigned long long* p) {
    unsigned long long v;
    asm volatile("ld.relaxed.gpu.global.u64 %0, [%1];" : "=l"(v) : "l"(p));
    return v;
}
__device__ __forceinline__ void st_relaxed_u64(unsigned long long* p, unsigned long long v) {
    asm volatile("st.relaxed.gpu.global.u64 [%0], %1;" :: "l"(p), "l"(v) : "memory");
}
// Packed f32x2 FMA (Blackwell): d = a*b + c elementwise on packed pairs.
__device__ __forceinline__ unsigned long long fma2(unsigned long long a, unsigned long long b,
                                                   unsigned long long c) {
    unsigned long long d;
    asm("fma.rn.f32x2 %0, %1, %2, %3;" : "=l"(d) : "l"(a), "l"(b), "l"(c));
    return d;
}
// 16B shared load directly into two packed u64 (avoids repack MOVs).
__device__ __forceinline__ void lds_v2_u64(unsigned addr, unsigned long long& a,
                                           unsigned long long& b) {
    asm volatile("ld.shared.v2.u64 {%0, %1}, [%2];" : "=l"(a), "=l"(b) : "r"(addr));
}
__device__ __forceinline__ float f2sum(unsigned long long v) {
    float lo = __uint_as_float((unsigned)v);
    float hi = __uint_as_float((unsigned)(v >> 32));
    return lo + hi;
}
__device__ __forceinline__ float sigf(float x) {
    return 1.0f / (1.0f + __expf(-x));   // __expf ~2ulp -> plenty for 1e-3
}
__device__ __forceinline__ float tanh_acc(float x) {
    // 1 - 2/(e^{2x}+1): overflow-safe (e->inf gives 1, e->0 gives -1)
    float e = __expf(2.0f * x);
    return 1.0f - 2.0f / (e + 1.0f);
}

// ---------------- x_gates = x @ W_ih.T + b_ih + b_hh ----------------
// 4096 rows, one warp per row. Launch 512 blocks x 256 threads = 4096 warps.
__global__ void xgates_kernel(const float* __restrict__ x, const float* __restrict__ Wih,
                              const float* __restrict__ bih, const float* __restrict__ bhh) {
    int lane = threadIdx.x & 31;
    int row  = blockIdx.x * 8 + (threadIdx.x >> 5);
    const float4* wr = (const float4*)(Wih + (size_t)row * HDIM);
    const float4* xr = (const float4*)x;
    float acc = 0.f;
    #pragma unroll
    for (int i = 0; i < 8; i++) {
        float4 w4 = wr[i * 32 + lane];
        float4 x4 = xr[i * 32 + lane];
        acc += w4.x * x4.x + w4.y * x4.y + w4.z * x4.z + w4.w * x4.w;
    }
    #pragma unroll
    for (int off = 16; off; off >>= 1) acc += __shfl_xor_sync(0xffffffffu, acc, off);
    if (lane == 0) g_xg[row] = acc + bih[row] + bhh[row];
}

// ---------------- persistent LSTM rollout ----------------
// 128 CTAs x 512 threads. CTA b owns h indices [8b, 8b+8): 32 gate rows.
// Warp w handles local rows 2w, 2w+1; lane l holds W_hh[row][i*128 + 4l .. +3] for i=0..7
// as packed f32x2 pairs (64 weight regs/thread).
__global__ void __launch_bounds__(TPB, 1)
lstm_kernel(const float* __restrict__ Whh, float* __restrict__ out, int N) {
    __shared__ float h_sm[HDIM];
    __shared__ float g_sm[32];

    const int tid  = threadIdx.x;
    const int lane = tid & 31;
    const int warp = tid >> 5;
    const int cta  = blockIdx.x;

    const int r0l = 2 * warp;          // local rows (gate*8 + j layout)
    const int r1l = 2 * warp + 1;
    const int gr0 = (r0l >> 3) * HDIM + cta * 8 + (r0l & 7);
    const int gr1 = (r1l >> 3) * HDIM + cta * 8 + (r1l & 7);

    // Pin weights in registers (one-time; also warms nothing else).
    ulonglong2 w0[8], w1[8];
    #pragma unroll
    for (int i = 0; i < 8; i++) {
        w0[i] = *(const ulonglong2*)(Whh + (size_t)gr0 * HDIM + i * 128 + lane * 4);
        w1[i] = *(const ulonglong2*)(Whh + (size_t)gr1 * HDIM + i * 128 + lane * 4);
    }
    const float xg0 = g_xg[gr0];
    const float xg1 = g_xg[gr1];

    const unsigned hs_base = (unsigned)__cvta_generic_to_shared(h_sm);
    const unsigned my_lds  = hs_base + (unsigned)(lane * 16);

    float c_state = 0.f;   // valid in tid<8 only

    for (int t = 0; t < N; t++) {
        // ---- acquire h(t): data-tagged poll (implicit global barrier) ----
        if (t == 0) {
            h_sm[tid] = 0.f;
            h_sm[tid + 512] = 0.f;
        } else {
            const unsigned long long* bp = g_hbuf[t & 1];
            const unsigned tag = (unsigned)t;
            unsigned long long v;
            do { v = ld_relaxed_u64(bp + tid); } while ((unsigned)(v >> 32) != tag);
            h_sm[tid] = __uint_as_float((unsigned)v);
            do { v = ld_relaxed_u64(bp + tid + 512); } while ((unsigned)(v >> 32) != tag);
            h_sm[tid + 512] = __uint_as_float((unsigned)v);
        }
        __syncthreads();

        // ---- matvec: 2 rows/warp, packed f32x2 FMAs ----
        unsigned long long a0p = 0ull, a0q = 0ull, a1p = 0ull, a1q = 0ull;
        #pragma unroll
        for (int i = 0; i < 8; i++) {
            unsigned long long hA, hB;
            lds_v2_u64(my_lds + (unsigned)(i * 512), hA, hB);
            a0p = fma2(w0[i].x, hA, a0p);
            a0q = fma2(w0[i].y, hB, a0q);
            a1p = fma2(w1[i].x, hA, a1p);
            a1q = fma2(w1[i].y, hB, a1q);
        }
        float s0 = f2sum(a0p) + f2sum(a0q);
        float s1 = f2sum(a1p) + f2sum(a1q);
        #pragma unroll
        for (int off = 16; off; off >>= 1) {
            s0 += __shfl_xor_sync(0xffffffffu, s0, off);
            s1 += __shfl_xor_sync(0xffffffffu, s1, off);
        }
        if (lane == 0) {
            g_sm[r0l] = s0 + xg0;
            g_sm[r1l] = s1 + xg1;
        }
        __syncthreads();

        // ---- nonlinearity + publish (8 lanes of warp 0) ----
        if (tid < 8) {
            float gi = g_sm[tid];
            float gf = g_sm[8 + tid];
            float gg = g_sm[16 + tid];
            float go = g_sm[24 + tid];
            float si = sigf(gi);
            float sf = sigf(gf);
            float sg = tanh_acc(gg);
            float so = sigf(go);
            c_state = sf * c_state + si * sg;
            float hv = so * tanh_acc(c_state);

            out[(size_t)t * HDIM + cta * 8 + tid] = hv;

            unsigned long long pv =
                ((unsigned long long)(unsigned)(t + 1) << 32) |
                (unsigned long long)__float_as_uint(hv);
            st_relaxed_u64(&g_hbuf[(t + 1) & 1][cta * 8 + tid], pv);
        }
        // No trailing barrier: next step's poll self-synchronizes; all h_sm/g_sm
        // hazards are covered by the two __syncthreads above (see design note).
    }
}

extern "C" void kernel_launch(void* const* d_in, const int* in_sizes, int n_in,
                              void* d_out, int out_size) {
    const float* x   = (const float*)d_in[0];
    const float* Wih = (const float*)d_in[1];
    const float* Whh = (const float*)d_in[2];
    const float* bih = (const float*)d_in[3];
    const float* bhh = (const float*)d_in[4];
    float* out = (float*)d_out;
    const int N = out_size / HDIM;   // num_nodes

    xgates_kernel<<<512, 256>>>(x, Wih, bih, bhh);
    lstm_kernel<<<NCTA, TPB>>>(Whh, out, N);
}